// round 11
// baseline (speedup 1.0000x reference)
#include <cuda_runtime.h>
#include <math.h>

#define NMESH 131072
#define NPIV  256
#define EDIM  64
#define BATCH 32
#define GM    64            // mesh grid dim (64x64 cells, ~32 pts/cell)
#define GP    16            // pivot grid dim (16x16 cells, ~1 pivot/cell)
#define NCM   (GM*GM)
#define NCP   (GP*GP)

// ---- scratch (no allocation allowed) ----
__device__ int    g_mcnt[NCM];
__device__ int    g_mcur[NCM];
__device__ int    g_csM [NCM + 1];
__device__ float2 g_msort[NMESH];
__device__ int    g_msortIdx[NMESH];
__device__ int    g_csP[NCP + 1];
__device__ float2 g_psort[NPIV];
__device__ int    g_prank[NPIV];
__device__ int    g_idx1[NPIV * 3];
__device__ float  g_c1  [NPIV * 3];
__device__ __align__(16) float g_q  [BATCH * NPIV * EDIM];
__device__ __align__(16) float g_Q  [BATCH * NPIV * EDIM];
__device__ __align__(16) float g_K  [BATCH * NPIV * EDIM];
__device__ float  g_y  [BATCH * NPIV * 3];          // [b][p][f]
__device__ __align__(16) float g_y2T[NPIV * BATCH * 3];  // [sorted_p][b][f]

// ---- helpers ----
__device__ __forceinline__ void ins3(float d, int i,
                                     float& d0, int& i0,
                                     float& d1, int& i1,
                                     float& d2, int& i2) {
    bool l2 = d < d2, l1 = d < d1, l0 = d < d0;
    float nd2 = l1 ? d1 : (l2 ? d : d2);  int ni2 = l1 ? i1 : (l2 ? i : i2);
    float nd1 = l0 ? d0 : (l1 ? d : d1);  int ni1 = l0 ? i0 : (l1 ? i : i1);
    float nd0 = l0 ? d  : d0;             int ni0 = l0 ? i  : i0;
    d0 = nd0; i0 = ni0; d1 = nd1; i1 = ni1; d2 = nd2; i2 = ni2;
}

__device__ __forceinline__ unsigned long long fma2(unsigned long long a,
                                                   unsigned long long b,
                                                   unsigned long long c) {
    unsigned long long d;
    asm("fma.rn.f32x2 %0,%1,%2,%3;" : "=l"(d) : "l"(a), "l"(b), "l"(c));
    return d;
}
__device__ __forceinline__ unsigned long long mul2(unsigned long long a,
                                                   unsigned long long b) {
    unsigned long long d;
    asm("mul.rn.f32x2 %0,%1,%2;" : "=l"(d) : "l"(a), "l"(b));
    return d;
}
__device__ __forceinline__ unsigned long long add2(unsigned long long a,
                                                   unsigned long long b) {
    unsigned long long d;
    asm("add.rn.f32x2 %0,%1,%2;" : "=l"(d) : "l"(a), "l"(b));
    return d;
}
__device__ __forceinline__ unsigned long long bcast2(float v) {
    unsigned long long d;
    asm("mov.b64 %0,{%1,%1};" : "=l"(d) : "f"(v));
    return d;
}
__device__ __forceinline__ void upk2(unsigned long long v, float& lo, float& hi) {
    asm("mov.b64 {%0,%1},%2;" : "=f"(lo), "=f"(hi) : "l"(v));
}

// ============ K0p: zero mesh-grid counters + build pivot grid ============
__global__ void k0p(const float2* __restrict__ pivp) {
    __shared__ int cnt[NCP];
    __shared__ int st[NCP + 1];
    int t = threadIdx.x;  // 256
    for (int i = t; i < NCM; i += 256) { g_mcnt[i] = 0; g_mcur[i] = 0; }
    cnt[t] = 0;
    float2 P = pivp[t];
    int cx = min(GP - 1, max(0, (int)(P.x * GP)));
    int cy = min(GP - 1, max(0, (int)(P.y * GP)));
    int cell = cy * GP + cx;
    __syncthreads();
    atomicAdd(&cnt[cell], 1);
    __syncthreads();
    if (t == 0) {
        int acc = 0;
        for (int i = 0; i < NCP; i++) { st[i] = acc; acc += cnt[i]; }
        st[NCP] = acc;
    }
    __syncthreads();
    cnt[t] = 0;
    __syncthreads();
    int pos = st[cell] + atomicAdd(&cnt[cell], 1);
    g_psort[pos] = P;
    g_prank[t] = pos;
    g_csP[t] = st[t];
    if (t == 0) g_csP[NCP] = st[NCP];
}

// ============ mesh grid: count / scan / scatter ============
__global__ void kmg_count(const float2* __restrict__ meshp) {
    int m = blockIdx.x * 256 + threadIdx.x;
    float2 P = meshp[m];
    int cx = min(GM - 1, max(0, (int)(P.x * GM)));
    int cy = min(GM - 1, max(0, (int)(P.y * GM)));
    atomicAdd(&g_mcnt[cy * GM + cx], 1);
}

__global__ void kmg_scan() {
    __shared__ int buf[2][NCM];
    int t = threadIdx.x;  // 1024
    for (int i = t; i < NCM; i += 1024) buf[0][i] = g_mcnt[i];
    __syncthreads();
    int cur = 0;
    for (int d = 1; d < NCM; d <<= 1) {
        for (int i = t; i < NCM; i += 1024) {
            int v = buf[cur][i];
            if (i >= d) v += buf[cur][i - d];
            buf[1 - cur][i] = v;
        }
        __syncthreads();
        cur ^= 1;
    }
    for (int i = t; i < NCM; i += 1024) g_csM[i + 1] = buf[cur][i];
    if (t == 0) g_csM[0] = 0;
}

__global__ void kmg_scatter(const float2* __restrict__ meshp) {
    int m = blockIdx.x * 256 + threadIdx.x;
    float2 P = meshp[m];
    int cx = min(GM - 1, max(0, (int)(P.x * GM)));
    int cy = min(GM - 1, max(0, (int)(P.y * GM)));
    int cell = cy * GM + cx;
    int dst = g_csM[cell] + atomicAdd(&g_mcur[cell], 1);
    g_msort[dst] = P;
    g_msortIdx[dst] = m;
}

// ============ K1q: pivot -> 3 nearest mesh nodes (warp per pivot, ring search) ============
__device__ __forceinline__ void scanRangeM(int lo, int hi, int lane, float px, float py,
                                           float& d0, int& i0, float& d1, int& i1,
                                           float& d2v, int& i2) {
    for (int s = lo + lane; s < hi; s += 32) {
        float2 q = g_msort[s];
        float dx = px - q.x, dy = py - q.y;
        float dd = fmaf(dx, dx, dy * dy);
        ins3(dd, s, d0, i0, d1, i1, d2v, i2);
    }
}

__global__ void k1q(const float2* __restrict__ pivp) {
    int w = (blockIdx.x << 3) + (threadIdx.x >> 5);  // pivot index
    int lane = threadIdx.x & 31;
    float2 P = pivp[w];
    int cx = min(GM - 1, max(0, (int)(P.x * GM)));
    int cy = min(GM - 1, max(0, (int)(P.y * GM)));
    float d0 = 3e38f, d1 = 3e38f, d2v = 3e38f;
    int i0 = 0, i1 = 0, i2 = 0;
    const float h = 1.f / GM;
    for (int r = 0; r < GM; r++) {
        int xlo = max(cx - r, 0), xhi = min(cx + r, GM - 1);
        if (r == 0) {
            int c = cy * GM + cx;
            scanRangeM(g_csM[c], g_csM[c + 1], lane, P.x, P.y, d0, i0, d1, i1, d2v, i2);
        } else {
            int yt = cy - r, yb = cy + r;
            if (yt >= 0) {
                int b0i = yt * GM;
                scanRangeM(g_csM[b0i + xlo], g_csM[b0i + xhi + 1], lane, P.x, P.y, d0, i0, d1, i1, d2v, i2);
            }
            if (yb < GM) {
                int b0i = yb * GM;
                scanRangeM(g_csM[b0i + xlo], g_csM[b0i + xhi + 1], lane, P.x, P.y, d0, i0, d1, i1, d2v, i2);
            }
            int yl2 = max(cy - r + 1, 0), yh2 = min(cy + r - 1, GM - 1);
            if (cx - r >= 0)
                for (int y = yl2; y <= yh2; y++) {
                    int c = y * GM + cx - r;
                    scanRangeM(g_csM[c], g_csM[c + 1], lane, P.x, P.y, d0, i0, d1, i1, d2v, i2);
                }
            if (cx + r < GM)
                for (int y = yl2; y <= yh2; y++) {
                    int c = y * GM + cx + r;
                    scanRangeM(g_csM[c], g_csM[c + 1], lane, P.x, P.y, d0, i0, d1, i1, d2v, i2);
                }
        }
        // warp-uniform termination: union-d3 <= min over lanes of lane-d3
        float mb = d2v;
#pragma unroll
        for (int off = 16; off; off >>= 1)
            mb = fminf(mb, __shfl_xor_sync(~0u, mb, off));
        float bd = r * h;
        if (mb <= bd * bd) break;
    }
    // clean binary-tree merge (lanes >= off frozen once consumed)
    for (int off = 16; off; off >>= 1) {
        float a0 = __shfl_down_sync(~0u, d0, off);
        float a1 = __shfl_down_sync(~0u, d1, off);
        float a2 = __shfl_down_sync(~0u, d2v, off);
        int   j0 = __shfl_down_sync(~0u, i0, off);
        int   j1 = __shfl_down_sync(~0u, i1, off);
        int   j2 = __shfl_down_sync(~0u, i2, off);
        if (lane < off) {
            ins3(a0, j0, d0, i0, d1, i1, d2v, i2);
            ins3(a1, j1, d0, i0, d1, i1, d2v, i2);
            ins3(a2, j2, d0, i0, d1, i1, d2v, i2);
        }
    }
    if (lane == 0) {
        float w0 = 1.f / fmaxf(d0, 1e-16f);
        float w1 = 1.f / fmaxf(d1, 1e-16f);
        float w2 = 1.f / fmaxf(d2v, 1e-16f);
        float inv = 1.f / (w0 + w1 + w2);
        g_idx1[w * 3 + 0] = g_msortIdx[i0];  g_c1[w * 3 + 0] = w0 * inv;
        g_idx1[w * 3 + 1] = g_msortIdx[i1];  g_c1[w * 3 + 1] = w1 * inv;
        g_idx1[w * 3 + 2] = g_msortIdx[i2];  g_c1[w * 3 + 2] = w2 * inv;
    }
}

// ============ K2a: gather + LN + interp + feature/pos projection -> q, y ============
__global__ void k2a(const float* __restrict__ node_attr, const float* __restrict__ pivp,
                    const float* __restrict__ gamma, const float* __restrict__ beta,
                    const float* __restrict__ Wf, const float* __restrict__ bf,
                    const float* __restrict__ Wp, const float* __restrict__ bpv) {
    int e = threadIdx.x;                 // 64 lanes = E
    int bp_ = blockIdx.x;
    int b = bp_ >> 8, p = bp_ & 255;
    float y0 = 0.f, y1 = 0.f, y2 = 0.f;
    float g0 = gamma[0], g1 = gamma[1], g2 = gamma[2];
    float be0 = beta[0], be1 = beta[1], be2 = beta[2];
#pragma unroll
    for (int k = 0; k < 3; k++) {
        int n = g_idx1[p * 3 + k];
        float c = g_c1[p * 3 + k];
        const float* a = node_attr + (b * NMESH + n) * 3;
        float a0 = a[0], a1 = a[1], a2 = a[2];
        float mu = (a0 + a1 + a2) * (1.f / 3.f);
        float e0 = a0 - mu, e1 = a1 - mu, e2 = a2 - mu;
        float var = (e0 * e0 + e1 * e1 + e2 * e2) * (1.f / 3.f);
        float r = rsqrtf(var + 1e-5f);
        y0 = fmaf(c, fmaf(e0 * r, g0, be0), y0);
        y1 = fmaf(c, fmaf(e1 * r, g1, be1), y1);
        y2 = fmaf(c, fmaf(e2 * r, g2, be2), y2);
    }
    float px = pivp[p * 2], py = pivp[p * 2 + 1];
    float qv = bf[e] + y0 * Wf[e * 3] + y1 * Wf[e * 3 + 1] + y2 * Wf[e * 3 + 2]
             + bpv[e] + px * Wp[e * 2] + py * Wp[e * 2 + 1];
    int row = b * 256 + p;
    g_q[row * 64 + e] = qv;
    if (e == 0) {
        g_y[row * 3 + 0] = y0;
        g_y[row * 3 + 1] = y1;
        g_y[row * 3 + 2] = y2;
    }
}

// ============ K2b: Q/K projection, 512 blocks x 128 thr, 32x64 tiles ============
__global__ void k2b(const float* __restrict__ W, const float* __restrict__ bias) {
    __shared__ float qs[32][65];
    __shared__ float ws[64][65];
    int r0 = blockIdx.x * 32;
    int half = blockIdx.y;               // 0 -> Q, 1 -> K
    int tid = threadIdx.x;               // 128
    const float4* qsrc = (const float4*)(g_q + r0 * 64);
#pragma unroll
    for (int k = 0; k < 4; k++) {
        int idx = tid + k * 128;
        int rr = idx >> 4, c4 = idx & 15;
        float4 v = qsrc[idx];
        float* d = &qs[rr][c4 * 4];
        d[0] = v.x; d[1] = v.y; d[2] = v.z; d[3] = v.w;
    }
    const float4* wsrc = (const float4*)(W + half * 64 * 64);
#pragma unroll
    for (int k = 0; k < 8; k++) {
        int idx = tid + k * 128;
        int rr = idx >> 4, c4 = idx & 15;
        float4 v = wsrc[idx];
        float* d = &ws[rr][c4 * 4];
        d[0] = v.x; d[1] = v.y; d[2] = v.z; d[3] = v.w;
    }
    __syncthreads();
    int tr = tid >> 4, tc = tid & 15;
    float acc[4][4];
#pragma unroll
    for (int j = 0; j < 4; j++) {
        float bv = bias[half * 64 + tc * 4 + j];
#pragma unroll
        for (int i = 0; i < 4; i++) acc[i][j] = bv;
    }
#pragma unroll 8
    for (int e = 0; e < 64; e++) {
        float a[4], bb[4];
#pragma unroll
        for (int i = 0; i < 4; i++) a[i] = qs[tr * 4 + i][e];
#pragma unroll
        for (int j = 0; j < 4; j++) bb[j] = ws[tc * 4 + j][e];
#pragma unroll
        for (int i = 0; i < 4; i++)
#pragma unroll
            for (int j = 0; j < 4; j++) acc[i][j] = fmaf(a[i], bb[j], acc[i][j]);
    }
    float* outp = half ? g_K : g_Q;
#pragma unroll
    for (int i = 0; i < 4; i++) {
        float4 v = make_float4(acc[i][0], acc[i][1], acc[i][2], acc[i][3]);
        *(float4*)(outp + (r0 + tr * 4 + i) * 64 + tc * 4) = v;
    }
}

// ============ K3: fused attention, packed f32x2 math ============
__global__ void k3() {
    extern __shared__ float sm[];
    float* Ks = sm;                          // 256*64 floats
    float4* ysAB = (float4*)(sm + 256 * 64); // 256 x (y0,y1,1,y2)
    int b = blockIdx.x >> 3, ic = blockIdx.x & 7;
    int tid = threadIdx.x;                   // 128 = 32 i x 4 h
    int il = tid >> 2, h = tid & 3;

    const float4* src = (const float4*)(g_K + b * 256 * 64);
    float4* dst = (float4*)Ks;
    for (int t = tid; t < 4096; t += 128) dst[t] = src[t];
    for (int t = tid; t < 256; t += 128) {
        const float* yr = g_y + b * 768 + t * 3;
        ysAB[t] = make_float4(yr[0], yr[1], 1.0f, yr[2]);
    }
    __syncthreads();

    int i = ic * 32 + il;
    const float SC = 0.25f * 1.4426950408889634f;  // fold 1/sqrt(DH) and log2(e)
    unsigned long long Qp[8];
    unsigned long long scp = bcast2(SC);
    const ulonglong2* qp = (const ulonglong2*)(g_Q + (b * 256 + i) * 64 + h * 16);
#pragma unroll
    for (int d = 0; d < 4; d++) {
        ulonglong2 v = qp[d];
        Qp[2 * d]     = mul2(v.x, scp);
        Qp[2 * d + 1] = mul2(v.y, scp);
    }
    unsigned long long accA = 0ULL, accB = 0ULL;  // (a0,a1), (l,a2)
    const ulonglong2* yab = (const ulonglong2*)ysAB;
#pragma unroll 2
    for (int j = 0; j < 256; j++) {
        const ulonglong2* kr = (const ulonglong2*)(Ks + j * 64 + h * 16);
        ulonglong2 k0 = kr[0], k1 = kr[1], k2 = kr[2], k3v = kr[3];
        unsigned long long sA = mul2(Qp[0], k0.x);
        sA = fma2(Qp[1], k0.y, sA);
        sA = fma2(Qp[2], k1.x, sA);
        sA = fma2(Qp[3], k1.y, sA);
        unsigned long long sB = mul2(Qp[4], k2.x);
        sB = fma2(Qp[5], k2.y, sB);
        sB = fma2(Qp[6], k3v.x, sB);
        sB = fma2(Qp[7], k3v.y, sB);
        sA = add2(sA, sB);
        float slo, shi;
        upk2(sA, slo, shi);
        float s = fminf(slo + shi, 126.f);
        float ev;
        asm("ex2.approx.f32 %0,%1;" : "=f"(ev) : "f"(s));
        unsigned long long evp = bcast2(ev);
        ulonglong2 ya = yab[j];
        accA = fma2(evp, ya.x, accA);
        accB = fma2(evp, ya.y, accB);
    }
    float a0, a1, l, a2;
    upk2(accA, a0, a1);
    upk2(accB, l, a2);
    float invl = 1.f / l;
    float r0 = a0 * invl, r1 = a1 * invl, r2 = a2 * invl;
    r0 += __shfl_xor_sync(~0u, r0, 1); r0 += __shfl_xor_sync(~0u, r0, 2);
    r1 += __shfl_xor_sync(~0u, r1, 1); r1 += __shfl_xor_sync(~0u, r1, 2);
    r2 += __shfl_xor_sync(~0u, r2, 1); r2 += __shfl_xor_sync(~0u, r2, 2);
    if (h == 0) {
        int o = (g_prank[i] * 32 + b) * 3;
        g_y2T[o + 0] = 0.25f * r0;
        g_y2T[o + 1] = 0.25f * r1;
        g_y2T[o + 2] = 0.25f * r2;
    }
}

// ============ K4: ring-search KNN pivotal->mesh + weighted scatter ============
__device__ __forceinline__ void scanP(int lo, int hi, float px, float py,
                                      const float2* pp,
                                      float& b0, float& b1, float& b2) {
    for (int s = lo; s < hi; s++) {
        float2 q = pp[s];
        float dx = px - q.x, dy = py - q.y;
        float dd = fmaf(dx, dx, dy * dy);
        float key = __uint_as_float((__float_as_uint(dd) & 0xFFFFFF00u) | (unsigned)s);
        float lo0 = fminf(key, b0), hi0 = fmaxf(key, b0);
        float lo1 = fminf(hi0, b1), hi1 = fmaxf(hi0, b1);
        b2 = fminf(hi1, b2); b0 = lo0; b1 = lo1;
    }
}

__global__ void k4(const float2* __restrict__ meshp, float* __restrict__ out) {
    extern __shared__ float sm[];
    float* ysm = sm;                          // 256 rows x 97 (pad kills conflicts)
    float2* pp = (float2*)(sm + 256 * 97);    // sorted pivot positions
    int* cs = (int*)(sm + 256 * 97 + 512);    // 257 cell starts
    int t = threadIdx.x;
    int m = blockIdx.x * 256 + t;
    pp[t] = g_psort[t];
    cs[t] = g_csP[t];
    if (t == 0) cs[NCP] = g_csP[NCP];
    {
        const float4* src = (const float4*)(g_y2T + t * 96);
        float* dr = ysm + t * 97;
#pragma unroll
        for (int c = 0; c < 24; c++) {
            float4 v = src[c];
            dr[4 * c + 0] = v.x; dr[4 * c + 1] = v.y;
            dr[4 * c + 2] = v.z; dr[4 * c + 3] = v.w;
        }
    }
    float2 MP = meshp[m];
    __syncthreads();

    int cx = min(GP - 1, max(0, (int)(MP.x * GP)));
    int cy = min(GP - 1, max(0, (int)(MP.y * GP)));
    float b0 = 3e38f, b1 = 3e38f, b2 = 3e38f;
    const float h = 1.f / GP;
    for (int r = 0; r < GP; r++) {
        int xlo = max(cx - r, 0), xhi = min(cx + r, GP - 1);
        if (r == 0) {
            int c = cy * GP + cx;
            scanP(cs[c], cs[c + 1], MP.x, MP.y, pp, b0, b1, b2);
        } else {
            int yt = cy - r, yb = cy + r;
            if (yt >= 0) {
                int c0 = yt * GP;
                scanP(cs[c0 + xlo], cs[c0 + xhi + 1], MP.x, MP.y, pp, b0, b1, b2);
            }
            if (yb < GP) {
                int c0 = yb * GP;
                scanP(cs[c0 + xlo], cs[c0 + xhi + 1], MP.x, MP.y, pp, b0, b1, b2);
            }
            int yl2 = max(cy - r + 1, 0), yh2 = min(cy + r - 1, GP - 1);
            if (cx - r >= 0)
                for (int y = yl2; y <= yh2; y++) {
                    int c = y * GP + cx - r;
                    scanP(cs[c], cs[c + 1], MP.x, MP.y, pp, b0, b1, b2);
                }
            if (cx + r < GP)
                for (int y = yl2; y <= yh2; y++) {
                    int c = y * GP + cx + r;
                    scanP(cs[c], cs[c + 1], MP.x, MP.y, pp, b0, b1, b2);
                }
        }
        float bd = r * h;
        if (b2 <= bd * bd) break;
    }
    int i0 = (int)(__float_as_uint(b0) & 0xFFu);
    int i1 = (int)(__float_as_uint(b1) & 0xFFu);
    int i2 = (int)(__float_as_uint(b2) & 0xFFu);
    float w0, w1, w2;
    {
        float2 q = pp[i0];
        float dx = MP.x - q.x, dy = MP.y - q.y;
        w0 = 1.f / fmaxf(fmaf(dx, dx, dy * dy), 1e-16f);
    }
    {
        float2 q = pp[i1];
        float dx = MP.x - q.x, dy = MP.y - q.y;
        w1 = 1.f / fmaxf(fmaf(dx, dx, dy * dy), 1e-16f);
    }
    {
        float2 q = pp[i2];
        float dx = MP.x - q.x, dy = MP.y - q.y;
        w2 = 1.f / fmaxf(fmaf(dx, dx, dy * dy), 1e-16f);
    }
    float invden = 1.f / (w0 + w1 + w2);
    w0 *= invden; w1 *= invden; w2 *= invden;

    const float* r0p = ysm + i0 * 97;
    const float* r1p = ysm + i1 * 97;
    const float* r2p = ysm + i2 * 97;
#pragma unroll 4
    for (int b = 0; b < 32; b++) {
        int c = b * 3;
        float o0 = fmaf(w2, r2p[c + 0], fmaf(w1, r1p[c + 0], w0 * r0p[c + 0]));
        float o1 = fmaf(w2, r2p[c + 1], fmaf(w1, r1p[c + 1], w0 * r0p[c + 1]));
        float o2 = fmaf(w2, r2p[c + 2], fmaf(w1, r1p[c + 2], w0 * r0p[c + 2]));
        int ob = (b * NMESH + m) * 3;
        out[ob + 0] = o0; out[ob + 1] = o1; out[ob + 2] = o2;
    }
}

extern "C" void kernel_launch(void* const* d_in, const int* in_sizes, int n_in,
                              void* d_out, int out_size) {
    const float* node_attr = (const float*)d_in[0];
    const float* meshp     = (const float*)d_in[1];
    const float* pivp      = (const float*)d_in[2];
    const float* gamma     = (const float*)d_in[3];
    const float* beta      = (const float*)d_in[4];
    const float* Wf        = (const float*)d_in[5];
    const float* bf        = (const float*)d_in[6];
    const float* Wp        = (const float*)d_in[7];
    const float* bpv       = (const float*)d_in[8];
    const float* Wio       = (const float*)d_in[9];
    const float* bio       = (const float*)d_in[10];
    float* out = (float*)d_out;

    size_t sm3 = (size_t)(256 * 64 + 256 * 4) * 4;            // 69632 B
    size_t sm4 = (size_t)(256 * 97 + 512) * 4 + (NCP + 1) * 4; // 102404 B
    cudaFuncSetAttribute(k3, cudaFuncAttributeMaxDynamicSharedMemorySize, (int)sm3);
    cudaFuncSetAttribute(k4, cudaFuncAttributeMaxDynamicSharedMemorySize, (int)sm4);

    k0p<<<1, 256>>>((const float2*)pivp);
    kmg_count<<<NMESH / 256, 256>>>((const float2*)meshp);
    kmg_scan<<<1, 1024>>>();
    kmg_scatter<<<NMESH / 256, 256>>>((const float2*)meshp);
    k1q<<<32, 256>>>((const float2*)pivp);
    k2a<<<BATCH * NPIV, 64>>>(node_attr, pivp, gamma, beta, Wf, bf, Wp, bpv);
    k2b<<<dim3(256, 2), 128>>>(Wio, bio);
    k3<<<256, 128, sm3>>>();
    k4<<<NMESH / 256, 256, sm4>>>((const float2*)meshp, out);
}